// round 4
// baseline (speedup 1.0000x reference)
#include <cuda_runtime.h>
#include <math.h>

#define E_  3072
#define D_  128
#define H_  8
#define HD_ 16
#define R_  64
#define FF_ 512
#define L_  3

// ---------------- scratch (no allocations allowed) ----------------
#define OFF_H    0
#define OFF_Q    393216
#define OFF_K    786432
#define OFF_V    1179648
#define OFF_ATT  1572864
#define OFF_A    1966080
#define OFF_MID  2359296
#define OFF_RBF  3932160
#define OFF_PX   4128768
#define OFF_X    4137984
#define OFF_META 4147200
#define TOTAL_F  4159488

__device__ __align__(16) float g_buf[TOTAL_F];

// ---------------- prep: edge meta + rbf ----------------
__global__ void prep_kernel(const int* __restrict__ ei, const int* __restrict__ bid,
                            const float* __restrict__ nc, int4* __restrict__ meta,
                            float* __restrict__ rbf) {
    int e = blockIdx.x * 128 + threadIdx.x;
    if (e >= E_) return;
    int s = ei[e], d = ei[E_ + e];
    meta[e] = make_int4(s, d, bid[s], bid[d]);
    float dx = nc[d*3+0] - nc[s*3+0];
    float dy = nc[d*3+1] - nc[s*3+1];
    float dz = nc[d*3+2] - nc[s*3+2];
    float dist = sqrtf(dx*dx + dy*dy + dz*dz);
    float t = fminf(dist * 0.1f, 1.0f);
    float fc = 0.5f * (cosf(3.14159265358979323846f * t) + 1.0f);
    const float inw = 64.0f / 10.0f;   // 1/width, width = CUTOFF/R
    #pragma unroll 8
    for (int r = 0; r < R_; r++) {
        float c = 10.0f * (float)r / 63.0f;   // linspace(0,10,64)
        float u = (dist - c) * inw;
        rbf[e * R_ + r] = expf(-u * u) * fc;
    }
}

// ---------------- utility kernels ----------------
__global__ void copy_kernel(float* __restrict__ dst, const float* __restrict__ src, int n) {
    int i = blockIdx.x * 256 + threadIdx.x;
    if (i < n) dst[i] = src[i];
}
__global__ void zero_kernel(float* __restrict__ dst, int n) {
    int i = blockIdx.x * 256 + threadIdx.x;
    if (i < n) dst[i] = 0.0f;
}

// ---------------- generic fp32 GEMM: C = [C +] A@B [+ bias] [silu] ----------------
// A [M,K] rm, B [K,N] rm, C [M,N] rm.  M%64==0, N%64==0, K%16==0 (holds for all calls)
__global__ void __launch_bounds__(256) gemm_kernel(
    const float* __restrict__ A, const float* __restrict__ B, float* __restrict__ C,
    int M, int N, int K, const float* __restrict__ bias, int addC, int act)
{
    __shared__ float As[64][16];
    __shared__ float Bs[16][64];
    int tid = threadIdx.x;
    int tx = tid & 15, ty = tid >> 4;
    int m0 = blockIdx.y << 6, n0 = blockIdx.x << 6;
    int am = tid >> 2, ak = (tid & 3) << 2;
    int bk = tid >> 4, bn = (tid & 15) << 2;
    float c[4][4] = {};
    for (int k0 = 0; k0 < K; k0 += 16) {
        *(float4*)&As[am][ak] = *(const float4*)&A[(m0 + am) * K + k0 + ak];
        *(float4*)&Bs[bk][bn] = *(const float4*)&B[(k0 + bk) * N + n0 + bn];
        __syncthreads();
        #pragma unroll
        for (int k = 0; k < 16; k++) {
            float a0 = As[ty*4+0][k], a1 = As[ty*4+1][k], a2 = As[ty*4+2][k], a3 = As[ty*4+3][k];
            float b0 = Bs[k][tx*4+0], b1 = Bs[k][tx*4+1], b2 = Bs[k][tx*4+2], b3 = Bs[k][tx*4+3];
            c[0][0] += a0*b0; c[0][1] += a0*b1; c[0][2] += a0*b2; c[0][3] += a0*b3;
            c[1][0] += a1*b0; c[1][1] += a1*b1; c[1][2] += a1*b2; c[1][3] += a1*b3;
            c[2][0] += a2*b0; c[2][1] += a2*b1; c[2][2] += a2*b2; c[2][3] += a2*b3;
            c[3][0] += a3*b0; c[3][1] += a3*b1; c[3][2] += a3*b2; c[3][3] += a3*b3;
        }
        __syncthreads();
    }
    int colb = n0 + tx * 4;
    float4 bv = make_float4(0.f, 0.f, 0.f, 0.f);
    if (bias) bv = *(const float4*)&bias[colb];
    #pragma unroll
    for (int i = 0; i < 4; i++) {
        int r = m0 + ty * 4 + i;
        float4 val = make_float4(c[i][0] + bv.x, c[i][1] + bv.y, c[i][2] + bv.z, c[i][3] + bv.w);
        if (addC) {
            float4 cv = *(const float4*)&C[r * N + colb];
            val.x += cv.x; val.y += cv.y; val.z += cv.z; val.w += cv.w;
        }
        if (act == 1) {  // silu
            val.x = val.x / (1.0f + __expf(-val.x));
            val.y = val.y / (1.0f + __expf(-val.y));
            val.z = val.z / (1.0f + __expf(-val.z));
            val.w = val.w / (1.0f + __expf(-val.w));
        }
        *(float4*)&C[r * N + colb] = val;
    }
}

// ---------------- masked multi-head attention (flash-style streaming softmax) ----
// grid (E/128, H), 512 threads. 4 lanes per query row (tg = tid&3), shfl-merged.
// INTRA also accumulates px[i] = mean_h sum_j p[h,i,j] * x[j]  (atomicAdd).
template<bool INTRA>
__global__ void __launch_bounds__(512) attn_kernel(
    const float* __restrict__ q, const float* __restrict__ k, const float* __restrict__ v,
    const int4* __restrict__ meta, const float* __restrict__ x,
    float* __restrict__ out, float* __restrict__ px)
{
    __shared__ float ks[64][20];   // stride 20 -> conflict-free, float4-aligned
    __shared__ float vs[64][20];
    __shared__ int4  ms[64];
    __shared__ float xs[192];
    int tid = threadIdx.x;
    int qi = tid >> 2, tg = tid & 3;
    int i = blockIdx.x * 128 + qi;
    int head = blockIdx.y;
    int off = head * HD_;

    float qr[16];
    #pragma unroll
    for (int c = 0; c < 4; c++) {
        float4 t = *(const float4*)&q[i * D_ + off + c * 4];
        qr[c*4+0] = t.x; qr[c*4+1] = t.y; qr[c*4+2] = t.z; qr[c*4+3] = t.w;
    }
    int4 mi = meta[i];

    float m = -1e30f, l = 0.0f;
    float acc[16];
    #pragma unroll
    for (int d = 0; d < 16; d++) acc[d] = 0.0f;
    float ax0 = 0.f, ax1 = 0.f, ax2 = 0.f;

    for (int j0 = 0; j0 < E_; j0 += 64) {
        {
            int t2 = tid & 255;
            int rid = t2 >> 2, c4 = (t2 & 3) << 2;
            if (tid < 256) *(float4*)&ks[rid][c4] = *(const float4*)&k[(j0 + rid) * D_ + off + c4];
            else           *(float4*)&vs[rid][c4] = *(const float4*)&v[(j0 + rid) * D_ + off + c4];
            if (tid < 64) ms[tid] = meta[j0 + tid];
            if (INTRA && tid >= 64 && tid < 256) xs[tid - 64] = x[j0 * 3 + (tid - 64)];
        }
        __syncthreads();
        for (int jj = tg; jj < 64; jj += 4) {
            int4 mj = ms[jj];
            bool ip = (mi.z == mj.z) && (mi.w == mj.w);
            int j = j0 + jj;
            bool mask;
            if (INTRA) {
                mask = ip || (i == j);
            } else {
                bool share = (mi.x == mj.x) || (mi.x == mj.y) || (mi.y == mj.x) || (mi.y == mj.y);
                mask = (share && !ip) || (i == j);
            }
            if (mask) {
                float s = 0.0f;
                #pragma unroll
                for (int d = 0; d < 16; d++) s += qr[d] * ks[jj][d];
                s *= 0.25f;   // 1/sqrt(16)
                if (s <= m) {
                    float p = __expf(s - m);
                    l += p;
                    #pragma unroll
                    for (int d = 0; d < 16; d++) acc[d] += p * vs[jj][d];
                    if (INTRA) { ax0 += p * xs[jj*3]; ax1 += p * xs[jj*3+1]; ax2 += p * xs[jj*3+2]; }
                } else {
                    float corr = __expf(m - s);
                    m = s;
                    l = l * corr + 1.0f;
                    #pragma unroll
                    for (int d = 0; d < 16; d++) acc[d] = acc[d] * corr + vs[jj][d];
                    if (INTRA) {
                        ax0 = ax0 * corr + xs[jj*3];
                        ax1 = ax1 * corr + xs[jj*3+1];
                        ax2 = ax2 * corr + xs[jj*3+2];
                    }
                }
            }
        }
        __syncthreads();
    }

    // merge the 4 partial softmax states per query (lanes differ in tg only)
    #pragma unroll
    for (int o2 = 1; o2 < 4; o2 <<= 1) {
        float m2 = __shfl_xor_sync(0xffffffffu, m, o2);
        float l2 = __shfl_xor_sync(0xffffffffu, l, o2);
        float mn = fmaxf(m, m2);
        float c1 = __expf(m - mn), c2 = __expf(m2 - mn);
        l = l * c1 + l2 * c2;
        #pragma unroll
        for (int d = 0; d < 16; d++) {
            float a2 = __shfl_xor_sync(0xffffffffu, acc[d], o2);
            acc[d] = acc[d] * c1 + a2 * c2;
        }
        if (INTRA) {
            float t0 = __shfl_xor_sync(0xffffffffu, ax0, o2);
            float t1 = __shfl_xor_sync(0xffffffffu, ax1, o2);
            float t2 = __shfl_xor_sync(0xffffffffu, ax2, o2);
            ax0 = ax0 * c1 + t0 * c2;
            ax1 = ax1 * c1 + t1 * c2;
            ax2 = ax2 * c1 + t2 * c2;
        }
        m = mn;
    }
    if (tg == 0) {
        float inv = 1.0f / l;   // diag is always unmasked -> l > 0
        #pragma unroll
        for (int c = 0; c < 4; c++) {
            float4 o4 = make_float4(acc[c*4]*inv, acc[c*4+1]*inv, acc[c*4+2]*inv, acc[c*4+3]*inv);
            *(float4*)&out[i * D_ + off + c * 4] = o4;
        }
        if (INTRA) {
            float w = inv * (1.0f / (float)H_);
            atomicAdd(&px[i*3+0], ax0 * w);
            atomicAdd(&px[i*3+1], ax1 * w);
            atomicAdd(&px[i*3+2], ax2 * w);
        }
    }
}

// ---------------- h = LayerNorm(h + a) ----------------
__global__ void __launch_bounds__(128) add_ln_kernel(
    float* __restrict__ h, const float* __restrict__ a,
    const float* __restrict__ g, const float* __restrict__ b)
{
    int row = blockIdx.x, tid = threadIdx.x;
    float t = h[row * D_ + tid] + a[row * D_ + tid];
    float s = t, sq = t * t;
    #pragma unroll
    for (int o = 16; o > 0; o >>= 1) {
        s  += __shfl_xor_sync(0xffffffffu, s,  o);
        sq += __shfl_xor_sync(0xffffffffu, sq, o);
    }
    __shared__ float ss[4], sqs[4];
    if ((tid & 31) == 0) { ss[tid >> 5] = s; sqs[tid >> 5] = sq; }
    __syncthreads();
    float S  = ss[0] + ss[1] + ss[2] + ss[3];
    float SQ = sqs[0] + sqs[1] + sqs[2] + sqs[3];
    float mean = S * (1.0f / 128.0f);
    float var = fmaxf(SQ * (1.0f / 128.0f) - mean * mean, 0.0f);
    float rstd = rsqrtf(var + 1e-5f);
    h[row * D_ + tid] = (t - mean) * rstd * g[tid] + b[tid];
}

// ---------------- gate = tanh(h@Wc + bc); x += gate*(x - px) ----------------
__global__ void __launch_bounds__(128) gate_kernel(
    const float* __restrict__ h, const float* __restrict__ Wc, const float* __restrict__ bc,
    const float* __restrict__ px, float* __restrict__ x)
{
    int row = blockIdx.x, tid = threadIdx.x;
    float s = h[row * D_ + tid] * Wc[tid];
    #pragma unroll
    for (int o = 16; o > 0; o >>= 1) s += __shfl_xor_sync(0xffffffffu, s, o);
    __shared__ float ss[4];
    if ((tid & 31) == 0) ss[tid >> 5] = s;
    __syncthreads();
    if (tid < 3) {
        float S = ss[0] + ss[1] + ss[2] + ss[3];
        float gt = tanhf(S + bc[0]);
        float xv = x[row * 3 + tid];
        x[row * 3 + tid] = xv + gt * (xv - px[row * 3 + tid]);
    }
}

// ---------------- output: concat(h, x) ----------------
__global__ void out_kernel(const float* __restrict__ h, const float* __restrict__ x,
                           float* __restrict__ out, int out_size)
{
    int i = blockIdx.x * 256 + threadIdx.x;
    if (i >= out_size) return;
    if (i < E_ * D_)            out[i] = h[i];
    else if (i < E_ * D_ + E_*3) out[i] = x[i - E_ * D_];
    else                         out[i] = 0.0f;
}

// ---------------- host ----------------
extern "C" void kernel_launch(void* const* d_in, const int* in_sizes, int n_in,
                              void* d_out, int out_size)
{
    const float* edge_features = (const float*)d_in[0];
    const float* edge_coords   = (const float*)d_in[1];
    const int*   edge_index    = (const int*)  d_in[2];
    const float* node_coords   = (const float*)d_in[3];
    const int*   block_ids     = (const int*)  d_in[4];
    const float* Wq_a = (const float*)d_in[5];
    const float* Wk_a = (const float*)d_in[6];
    const float* Wv_a = (const float*)d_in[7];
    const float* Wo_a = (const float*)d_in[8];
    const float* Wq_e = (const float*)d_in[9];
    const float* Wk_e = (const float*)d_in[10];
    const float* Wv_e = (const float*)d_in[11];
    const float* Wo_e = (const float*)d_in[12];
    const float* W1   = (const float*)d_in[13];
    const float* b1   = (const float*)d_in[14];
    const float* W2   = (const float*)d_in[15];
    const float* b2   = (const float*)d_in[16];
    const float* ln1g = (const float*)d_in[17];
    const float* ln1b = (const float*)d_in[18];
    const float* ln2g = (const float*)d_in[19];
    const float* ln2b = (const float*)d_in[20];
    const float* ln3g = (const float*)d_in[21];
    const float* ln3b = (const float*)d_in[22];
    const float* Wrbf = (const float*)d_in[23];
    const float* Wc   = (const float*)d_in[24];
    const float* bc   = (const float*)d_in[25];

    float* buf = nullptr;
    cudaGetSymbolAddress((void**)&buf, g_buf);
    float* h    = buf + OFF_H;
    float* qb   = buf + OFF_Q;
    float* kb   = buf + OFF_K;
    float* vb   = buf + OFF_V;
    float* att  = buf + OFF_ATT;
    float* ab   = buf + OFF_A;
    float* mid  = buf + OFF_MID;
    float* rbf  = buf + OFF_RBF;
    float* px   = buf + OFF_PX;
    float* xb   = buf + OFF_X;
    int4*  meta = (int4*)(buf + OFF_META);

    dim3 gProj(D_ / 64, E_ / 64);    // N=128
    dim3 gFF1(FF_ / 64, E_ / 64);    // N=512
    dim3 gAttn(E_ / 128, H_);

    prep_kernel<<<(E_ + 127) / 128, 128>>>(edge_index, block_ids, node_coords, meta, rbf);
    copy_kernel<<<(E_ * D_ + 255) / 256, 256>>>(h, edge_features, E_ * D_);
    copy_kernel<<<(E_ * 3 + 255) / 256, 256>>>(xb, edge_coords, E_ * 3);

    for (int l = 0; l < L_; l++) {
        const int DD = D_ * D_;
        // h += rbf @ Wrbf[l]
        gemm_kernel<<<gProj, 256>>>(rbf, Wrbf + l * R_ * D_, h, E_, D_, R_, nullptr, 1, 0);

        // --- intra attention ---
        gemm_kernel<<<gProj, 256>>>(h, Wq_a + l * DD, qb, E_, D_, D_, nullptr, 0, 0);
        gemm_kernel<<<gProj, 256>>>(h, Wk_a + l * DD, kb, E_, D_, D_, nullptr, 0, 0);
        gemm_kernel<<<gProj, 256>>>(h, Wv_a + l * DD, vb, E_, D_, D_, nullptr, 0, 0);
        zero_kernel<<<(E_ * 3 + 255) / 256, 256>>>(px, E_ * 3);
        attn_kernel<true><<<gAttn, 512>>>(qb, kb, vb, meta, xb, att, px);
        gemm_kernel<<<gProj, 256>>>(att, Wo_a + l * DD, ab, E_, D_, D_, nullptr, 0, 0);
        add_ln_kernel<<<E_, 128>>>(h, ab, ln1g + l * D_, ln1b + l * D_);

        // --- inter attention ---
        gemm_kernel<<<gProj, 256>>>(h, Wq_e + l * DD, qb, E_, D_, D_, nullptr, 0, 0);
        gemm_kernel<<<gProj, 256>>>(h, Wk_e + l * DD, kb, E_, D_, D_, nullptr, 0, 0);
        gemm_kernel<<<gProj, 256>>>(h, Wv_e + l * DD, vb, E_, D_, D_, nullptr, 0, 0);
        attn_kernel<false><<<gAttn, 512>>>(qb, kb, vb, meta, xb, att, nullptr);
        gemm_kernel<<<gProj, 256>>>(att, Wo_e + l * DD, ab, E_, D_, D_, nullptr, 0, 0);
        add_ln_kernel<<<E_, 128>>>(h, ab, ln2g + l * D_, ln2b + l * D_);

        // --- FFN ---
        gemm_kernel<<<gFF1, 256>>>(h, W1 + l * D_ * FF_, mid, E_, FF_, D_, b1 + l * FF_, 0, 1);
        gemm_kernel<<<gProj, 256>>>(mid, W2 + l * FF_ * D_, ab, E_, D_, FF_, b2 + l * D_, 0, 0);
        add_ln_kernel<<<E_, 128>>>(h, ab, ln3g + l * D_, ln3b + l * D_);

        // --- coordinate update ---
        gate_kernel<<<E_, 128>>>(h, Wc + l * D_, bc + l, px, xb);
    }

    out_kernel<<<(out_size + 255) / 256, 256>>>(h, xb, (float*)d_out, out_size);
}

// round 6
// speedup vs baseline: 2.9216x; 2.9216x over previous
#include <cuda_runtime.h>
#include <math.h>

#define E_   3072
#define D_   128
#define H_   8
#define HD_  16
#define R_   64
#define FF_  512
#define L_   3
#define CAP_ 128

// ---------------- scratch (no allocations allowed) ----------------
#define OFF_H    0
#define OFF_Q    393216
#define OFF_K    786432
#define OFF_V    1179648
#define OFF_ATT  1572864
#define OFF_A    1966080
#define OFF_MID  2359296
#define OFF_RBF  3932160
#define OFF_PX   4128768
#define OFF_X    4137984
#define OFF_META 4147200
#define TOTAL_F  4159488

__device__ __align__(16) float g_buf[TOTAL_F];
__device__ int g_ilist[E_ * CAP_];
__device__ int g_xlist[E_ * CAP_];
__device__ int g_icnt[E_];
__device__ int g_xcnt[E_];

// ---------------- prep: edge meta + rbf + zero px ----------------
__global__ void prep_kernel(const int* __restrict__ ei, const int* __restrict__ bid,
                            const float* __restrict__ nc, int4* __restrict__ meta,
                            float* __restrict__ rbf, float* __restrict__ px) {
    int e = blockIdx.x * 128 + threadIdx.x;
    if (e >= E_) return;
    int s = ei[e], d = ei[E_ + e];
    meta[e] = make_int4(s, d, bid[s], bid[d]);
    px[e*3+0] = 0.f; px[e*3+1] = 0.f; px[e*3+2] = 0.f;
    float dx = nc[d*3+0] - nc[s*3+0];
    float dy = nc[d*3+1] - nc[s*3+1];
    float dz = nc[d*3+2] - nc[s*3+2];
    float dist = sqrtf(dx*dx + dy*dy + dz*dz);
    float t = fminf(dist * 0.1f, 1.0f);
    float fc = 0.5f * (cosf(3.14159265358979323846f * t) + 1.0f);
    const float inw = 64.0f / 10.0f;   // 1/width, width = CUTOFF/R
    #pragma unroll 8
    for (int r = 0; r < R_; r++) {
        float c = 10.0f * (float)r / 63.0f;   // linspace(0,10,64)
        float u = (dist - c) * inw;
        rbf[e * R_ + r] = expf(-u * u) * fc;
    }
}

// ---------------- build neighbor lists (once; layer/head-invariant) ----------
__global__ void __launch_bounds__(128) build_kernel(const int4* __restrict__ meta) {
    __shared__ int ci, cx;
    int i = blockIdx.x, tid = threadIdx.x;
    if (tid == 0) { ci = 0; cx = 0; }
    __syncthreads();
    int4 mi = meta[i];
    for (int j = tid; j < E_; j += 128) {
        int4 mj = meta[j];
        bool ip = (mi.z == mj.z) && (mi.w == mj.w);
        bool share = (mi.x == mj.x) || (mi.x == mj.y) || (mi.y == mj.x) || (mi.y == mj.y);
        if (ip || (i == j)) {
            int p = atomicAdd(&ci, 1);
            if (p < CAP_) g_ilist[i * CAP_ + p] = j;
        }
        if ((share && !ip) || (i == j)) {
            int p = atomicAdd(&cx, 1);
            if (p < CAP_) g_xlist[i * CAP_ + p] = j;
        }
    }
    __syncthreads();
    if (tid == 0) {
        g_icnt[i] = min(ci, CAP_);
        g_xcnt[i] = min(cx, CAP_);
    }
}

// ---------------- utility ----------------
__global__ void copy_kernel(float* __restrict__ dst, const float* __restrict__ src, int n) {
    int i = blockIdx.x * 256 + threadIdx.x;
    if (i < n) dst[i] = src[i];
}

// ---------------- fp32 GEMM: C = [C +] A@B [+ bias] [silu] ---------------------
// A [M,K] rm, B [K,N] rm, C [M,N] rm. Tiles 32x64, BK=16, 128 threads, 4x4 micro.
// blockIdx.z selects B among {B0,B1,B2} and offsets C by z*M*N (batched QKV).
__global__ void __launch_bounds__(128) gemm_kernel(
    const float* __restrict__ A, const float* __restrict__ B0,
    const float* __restrict__ B1, const float* __restrict__ B2,
    float* __restrict__ Cb, int M, int N, int K,
    const float* __restrict__ bias, int addC, int act)
{
    __shared__ float As[32][16];
    __shared__ float Bs[16][64];
    const float* B = (blockIdx.z == 0) ? B0 : ((blockIdx.z == 1) ? B1 : B2);
    float* C = Cb + (size_t)blockIdx.z * (size_t)M * N;
    int tid = threadIdx.x;
    int tx = tid & 15, ty = tid >> 4;
    int m0 = blockIdx.y << 5, n0 = blockIdx.x << 6;
    int am = tid >> 2, ak = (tid & 3) << 2;
    int bk = tid >> 4, bn = (tid & 15) << 2;
    float c[4][4] = {};
    for (int k0 = 0; k0 < K; k0 += 16) {
        *(float4*)&As[am][ak]     = *(const float4*)&A[(m0 + am) * K + k0 + ak];
        *(float4*)&Bs[bk][bn]     = *(const float4*)&B[(k0 + bk) * N + n0 + bn];
        *(float4*)&Bs[bk + 8][bn] = *(const float4*)&B[(k0 + bk + 8) * N + n0 + bn];
        __syncthreads();
        #pragma unroll
        for (int k = 0; k < 16; k++) {
            float4 bv = *(const float4*)&Bs[k][tx << 2];
            float a0 = As[ty*4+0][k], a1 = As[ty*4+1][k];
            float a2 = As[ty*4+2][k], a3 = As[ty*4+3][k];
            c[0][0] += a0*bv.x; c[0][1] += a0*bv.y; c[0][2] += a0*bv.z; c[0][3] += a0*bv.w;
            c[1][0] += a1*bv.x; c[1][1] += a1*bv.y; c[1][2] += a1*bv.z; c[1][3] += a1*bv.w;
            c[2][0] += a2*bv.x; c[2][1] += a2*bv.y; c[2][2] += a2*bv.z; c[2][3] += a2*bv.w;
            c[3][0] += a3*bv.x; c[3][1] += a3*bv.y; c[3][2] += a3*bv.z; c[3][3] += a3*bv.w;
        }
        __syncthreads();
    }
    int colb = n0 + tx * 4;
    float4 bv = make_float4(0.f, 0.f, 0.f, 0.f);
    if (bias) bv = *(const float4*)&bias[colb];
    #pragma unroll
    for (int i = 0; i < 4; i++) {
        int r = m0 + ty * 4 + i;
        float4 val = make_float4(c[i][0] + bv.x, c[i][1] + bv.y, c[i][2] + bv.z, c[i][3] + bv.w);
        if (addC) {
            float4 cv = *(const float4*)&C[r * N + colb];
            val.x += cv.x; val.y += cv.y; val.z += cv.z; val.w += cv.w;
        }
        if (act == 1) {  // silu
            val.x = val.x / (1.0f + __expf(-val.x));
            val.y = val.y / (1.0f + __expf(-val.y));
            val.z = val.z / (1.0f + __expf(-val.z));
            val.w = val.w / (1.0f + __expf(-val.w));
        }
        *(float4*)&C[r * N + colb] = val;
    }
}

// ---------------- sparse masked attention: one warp per (query, head) -----------
// Lanes split as (half, d): d = lane&15 is the head-dim, half = lane>>4 splits the
// neighbor list. Streaming softmax; halves merged via shfl at the end.
// IMPORTANT: in-loop shuffles use per-half masks — the two halves have different
// trip counts when n is odd, so a full-warp mask there is UB (R4's bug).
// INTRA also accumulates px[i] = mean_h sum_j p[h,i,j] * x[j] (atomicAdd, 3 lanes).
template<bool INTRA>
__global__ void __launch_bounds__(256) attn_kernel(
    const float* __restrict__ q, const float* __restrict__ k, const float* __restrict__ v,
    const float* __restrict__ x, float* __restrict__ out, float* __restrict__ px)
{
    int warp = threadIdx.x >> 5, lane = threadIdx.x & 31;
    int i = blockIdx.x * 8 + warp;
    int head = blockIdx.y;
    int off = head * HD_;
    int d = lane & 15, half = lane >> 4;
    unsigned hm = half ? 0xffff0000u : 0x0000ffffu;   // lanes of MY half only

    float qd = q[i * D_ + off + d];
    int n = INTRA ? g_icnt[i] : g_xcnt[i];
    const int* li = (INTRA ? g_ilist : g_xlist) + i * CAP_;

    float m = -1e30f, l = 0.0f, acc = 0.0f, ax = 0.0f;

    for (int t = half; t < n; t += 2) {
        int j = li[t];
        float s = qd * k[j * D_ + off + d];
        s += __shfl_xor_sync(hm, s, 8);
        s += __shfl_xor_sync(hm, s, 4);
        s += __shfl_xor_sync(hm, s, 2);
        s += __shfl_xor_sync(hm, s, 1);
        s *= 0.25f;  // 1/sqrt(16)
        float vd = v[j * D_ + off + d];
        float mn = fmaxf(m, s);
        float cc = __expf(m - mn), p = __expf(s - mn);
        l = l * cc + p;
        acc = acc * cc + p * vd;
        if (INTRA && d < 3) ax = ax * cc + p * x[j * 3 + d];
        m = mn;
    }

    // merge the two halves (all 32 lanes re-converged here -> full mask is legal)
    float m2 = __shfl_xor_sync(0xffffffffu, m, 16);
    float l2 = __shfl_xor_sync(0xffffffffu, l, 16);
    float a2 = __shfl_xor_sync(0xffffffffu, acc, 16);
    float mn = fmaxf(m, m2);
    float c1 = __expf(m - mn), c2 = __expf(m2 - mn);
    l = l * c1 + l2 * c2;
    acc = acc * c1 + a2 * c2;
    if (INTRA) {
        float x2 = __shfl_xor_sync(0xffffffffu, ax, 16);
        ax = ax * c1 + x2 * c2;
    }
    float inv = 1.0f / l;  // diag always present -> l > 0
    if (half == 0) {
        out[i * D_ + off + d] = acc * inv;
        if (INTRA && d < 3) atomicAdd(&px[i * 3 + d], ax * inv * 0.125f);
    }
}

// ---------------- h = LayerNorm(h + a) ----------------
__global__ void __launch_bounds__(128) add_ln_kernel(
    float* __restrict__ h, const float* __restrict__ a,
    const float* __restrict__ g, const float* __restrict__ b)
{
    int row = blockIdx.x, tid = threadIdx.x;
    float t = h[row * D_ + tid] + a[row * D_ + tid];
    float s = t, sq = t * t;
    #pragma unroll
    for (int o = 16; o > 0; o >>= 1) {
        s  += __shfl_xor_sync(0xffffffffu, s,  o);
        sq += __shfl_xor_sync(0xffffffffu, sq, o);
    }
    __shared__ float ss[4], sqs[4];
    if ((tid & 31) == 0) { ss[tid >> 5] = s; sqs[tid >> 5] = sq; }
    __syncthreads();
    float S  = ss[0] + ss[1] + ss[2] + ss[3];
    float SQ = sqs[0] + sqs[1] + sqs[2] + sqs[3];
    float mean = S * (1.0f / 128.0f);
    float var = fmaxf(SQ * (1.0f / 128.0f) - mean * mean, 0.0f);
    float rstd = rsqrtf(var + 1e-5f);
    h[row * D_ + tid] = (t - mean) * rstd * g[tid] + b[tid];
}

// ------ gate = tanh(h@Wc + bc); x += gate*(x - px); then zero px for next layer --
__global__ void __launch_bounds__(128) gate_kernel(
    const float* __restrict__ h, const float* __restrict__ Wc, const float* __restrict__ bc,
    float* __restrict__ px, float* __restrict__ x)
{
    int row = blockIdx.x, tid = threadIdx.x;
    float s = h[row * D_ + tid] * Wc[tid];
    #pragma unroll
    for (int o = 16; o > 0; o >>= 1) s += __shfl_xor_sync(0xffffffffu, s, o);
    __shared__ float ss[4];
    if ((tid & 31) == 0) ss[tid >> 5] = s;
    __syncthreads();
    if (tid < 3) {
        float S = ss[0] + ss[1] + ss[2] + ss[3];
        float gt = tanhf(S + bc[0]);
        float xv = x[row * 3 + tid];
        x[row * 3 + tid] = xv + gt * (xv - px[row * 3 + tid]);
        px[row * 3 + tid] = 0.0f;   // ready for next layer / next replay
    }
}

// ---------------- output: concat(h, x) ----------------
__global__ void out_kernel(const float* __restrict__ h, const float* __restrict__ x,
                           float* __restrict__ out, int out_size)
{
    int i = blockIdx.x * 256 + threadIdx.x;
    if (i >= out_size) return;
    if (i < E_ * D_)              out[i] = h[i];
    else if (i < E_ * D_ + E_ * 3) out[i] = x[i - E_ * D_];
    else                           out[i] = 0.0f;
}

// ---------------- host ----------------
extern "C" void kernel_launch(void* const* d_in, const int* in_sizes, int n_in,
                              void* d_out, int out_size)
{
    const float* edge_features = (const float*)d_in[0];
    const float* edge_coords   = (const float*)d_in[1];
    const int*   edge_index    = (const int*)  d_in[2];
    const float* node_coords   = (const float*)d_in[3];
    const int*   block_ids     = (const int*)  d_in[4];
    const float* Wq_a = (const float*)d_in[5];
    const float* Wk_a = (const float*)d_in[6];
    const float* Wv_a = (const float*)d_in[7];
    const float* Wo_a = (const float*)d_in[8];
    const float* Wq_e = (const float*)d_in[9];
    const float* Wk_e = (const float*)d_in[10];
    const float* Wv_e = (const float*)d_in[11];
    const float* Wo_e = (const float*)d_in[12];
    const float* W1   = (const float*)d_in[13];
    const float* b1   = (const float*)d_in[14];
    const float* W2   = (const float*)d_in[15];
    const float* b2   = (const float*)d_in[16];
    const float* ln1g = (const float*)d_in[17];
    const float* ln1b = (const float*)d_in[18];
    const float* ln2g = (const float*)d_in[19];
    const float* ln2b = (const float*)d_in[20];
    const float* ln3g = (const float*)d_in[21];
    const float* ln3b = (const float*)d_in[22];
    const float* Wrbf = (const float*)d_in[23];
    const float* Wc   = (const float*)d_in[24];
    const float* bc   = (const float*)d_in[25];

    float* buf = nullptr;
    cudaGetSymbolAddress((void**)&buf, g_buf);
    float* h    = buf + OFF_H;
    float* qb   = buf + OFF_Q;     // q,k,v contiguous -> batched GEMM dst
    float* kb   = buf + OFF_K;
    float* vb   = buf + OFF_V;
    float* att  = buf + OFF_ATT;
    float* ab   = buf + OFF_A;
    float* mid  = buf + OFF_MID;
    float* rbf  = buf + OFF_RBF;
    float* px   = buf + OFF_PX;
    float* xb   = buf + OFF_X;
    int4*  meta = (int4*)(buf + OFF_META);

    dim3 gProj(D_ / 64, E_ / 32, 1);    // 192 blocks
    dim3 gQKV(D_ / 64, E_ / 32, 3);     // 576 blocks
    dim3 gFF1(FF_ / 64, E_ / 32, 1);    // 768 blocks
    dim3 gAttn(E_ / 8, H_);             // warp per (i, head)

    prep_kernel<<<(E_ + 127) / 128, 128>>>(edge_index, block_ids, node_coords, meta, rbf, px);
    build_kernel<<<E_, 128>>>(meta);
    copy_kernel<<<(E_ * D_ + 255) / 256, 256>>>(h, edge_features, E_ * D_);
    copy_kernel<<<(E_ * 3 + 255) / 256, 256>>>(xb, edge_coords, E_ * 3);

    for (int l = 0; l < L_; l++) {
        const int DD = D_ * D_;
        // h += rbf @ Wrbf[l]
        gemm_kernel<<<gProj, 128>>>(rbf, Wrbf + l * R_ * D_, nullptr, nullptr, h,
                                    E_, D_, R_, nullptr, 1, 0);

        // --- intra attention ---
        gemm_kernel<<<gQKV, 128>>>(h, Wq_a + l * DD, Wk_a + l * DD, Wv_a + l * DD, qb,
                                   E_, D_, D_, nullptr, 0, 0);
        attn_kernel<true><<<gAttn, 256>>>(qb, kb, vb, xb, att, px);
        gemm_kernel<<<gProj, 128>>>(att, Wo_a + l * DD, nullptr, nullptr, ab,
                                    E_, D_, D_, nullptr, 0, 0);
        add_ln_kernel<<<E_, 128>>>(h, ab, ln1g + l * D_, ln1b + l * D_);

        // --- inter attention ---
        gemm_kernel<<<gQKV, 128>>>(h, Wq_e + l * DD, Wk_e + l * DD, Wv_e + l * DD, qb,
                                   E_, D_, D_, nullptr, 0, 0);
        attn_kernel<false><<<gAttn, 256>>>(qb, kb, vb, xb, att, nullptr);
        gemm_kernel<<<gProj, 128>>>(att, Wo_e + l * DD, nullptr, nullptr, ab,
                                    E_, D_, D_, nullptr, 0, 0);
        add_ln_kernel<<<E_, 128>>>(h, ab, ln2g + l * D_, ln2b + l * D_);

        // --- FFN ---
        gemm_kernel<<<gFF1, 128>>>(h, W1 + l * D_ * FF_, nullptr, nullptr, mid,
                                   E_, FF_, D_, b1 + l * FF_, 0, 1);
        gemm_kernel<<<gProj, 128>>>(mid, W2 + l * FF_ * D_, nullptr, nullptr, ab,
                                    E_, D_, FF_, b2 + l * D_, 0, 0);
        add_ln_kernel<<<E_, 128>>>(h, ab, ln3g + l * D_, ln3b + l * D_);

        // --- coordinate update (also zeros px for next layer) ---
        gate_kernel<<<E_, 128>>>(h, Wc + l * D_, bc + l, px, xb);
    }

    out_kernel<<<(out_size + 255) / 256, 256>>>(h, xb, (float*)d_out, out_size);
}

// round 7
// speedup vs baseline: 2.9929x; 1.0244x over previous
#include <cuda_runtime.h>
#include <math.h>

#define E_   3072
#define D_   128
#define H_   8
#define HD_  16
#define R_   64
#define FF_  512
#define L_   3
#define CAP_ 128

// ---------------- scratch (no allocations allowed) ----------------
#define OFF_H    0
#define OFF_Q    393216
#define OFF_K    786432
#define OFF_V    1179648
#define OFF_ATT  1572864
#define OFF_A    1966080
#define OFF_MID  2359296
#define OFF_RBF  3932160
#define OFF_PX   4128768
#define OFF_X    4137984
#define OFF_META 4147200
#define TOTAL_F  4159488

__device__ __align__(16) float g_buf[TOTAL_F];
__device__ int g_ilist[E_ * CAP_];
__device__ int g_xlist[E_ * CAP_];
__device__ int g_icnt[E_];
__device__ int g_xcnt[E_];

// ---------------- packed f32x2 helpers (Blackwell FFMA2) ----------------
typedef unsigned long long ull;
__device__ __forceinline__ ull pack2(float lo, float hi) {
    ull r; asm("mov.b64 %0, {%1, %2};" : "=l"(r) : "f"(lo), "f"(hi)); return r;
}
__device__ __forceinline__ ull dup2(float v) {
    ull r; asm("mov.b64 %0, {%1, %1};" : "=l"(r) : "f"(v)); return r;
}
__device__ __forceinline__ ull fma2(ull a, ull b, ull c) {
    ull d; asm("fma.rn.f32x2 %0, %1, %2, %3;" : "=l"(d) : "l"(a), "l"(b), "l"(c)); return d;
}
__device__ __forceinline__ float2 unpk(ull v) {
    float lo, hi; asm("mov.b64 {%0, %1}, %2;" : "=f"(lo), "=f"(hi) : "l"(v));
    return make_float2(lo, hi);
}

// ---------------- prep: edge meta + rbf + zero px ----------------
__global__ void prep_kernel(const int* __restrict__ ei, const int* __restrict__ bid,
                            const float* __restrict__ nc, int4* __restrict__ meta,
                            float* __restrict__ rbf, float* __restrict__ px) {
    int e = blockIdx.x * 128 + threadIdx.x;
    if (e >= E_) return;
    int s = ei[e], d = ei[E_ + e];
    meta[e] = make_int4(s, d, bid[s], bid[d]);
    px[e*3+0] = 0.f; px[e*3+1] = 0.f; px[e*3+2] = 0.f;
    float dx = nc[d*3+0] - nc[s*3+0];
    float dy = nc[d*3+1] - nc[s*3+1];
    float dz = nc[d*3+2] - nc[s*3+2];
    float dist = sqrtf(dx*dx + dy*dy + dz*dz);
    float t = fminf(dist * 0.1f, 1.0f);
    float fc = 0.5f * (cosf(3.14159265358979323846f * t) + 1.0f);
    const float inw = 64.0f / 10.0f;   // 1/width, width = CUTOFF/R
    #pragma unroll 8
    for (int r = 0; r < R_; r++) {
        float c = 10.0f * (float)r / 63.0f;   // linspace(0,10,64)
        float u = (dist - c) * inw;
        rbf[e * R_ + r] = expf(-u * u) * fc;
    }
}

// ---------------- build neighbor lists (once; layer/head-invariant) ----------
__global__ void __launch_bounds__(128) build_kernel(const int4* __restrict__ meta) {
    __shared__ int ci, cx;
    int i = blockIdx.x, tid = threadIdx.x;
    if (tid == 0) { ci = 0; cx = 0; }
    __syncthreads();
    int4 mi = meta[i];
    for (int j = tid; j < E_; j += 128) {
        int4 mj = meta[j];
        bool ip = (mi.z == mj.z) && (mi.w == mj.w);
        bool share = (mi.x == mj.x) || (mi.x == mj.y) || (mi.y == mj.x) || (mi.y == mj.y);
        if (ip || (i == j)) {
            int p = atomicAdd(&ci, 1);
            if (p < CAP_) g_ilist[i * CAP_ + p] = j;
        }
        if ((share && !ip) || (i == j)) {
            int p = atomicAdd(&cx, 1);
            if (p < CAP_) g_xlist[i * CAP_ + p] = j;
        }
    }
    __syncthreads();
    if (tid == 0) {
        g_icnt[i] = min(ci, CAP_);
        g_xcnt[i] = min(cx, CAP_);
    }
}

// ---------------- utility ----------------
__global__ void copy_kernel(float* __restrict__ dst, const float* __restrict__ src, int n) {
    int i = blockIdx.x * 256 + threadIdx.x;
    if (i < n) dst[i] = src[i];
}

// ============ fused GEMM, tile 32x128, 256 threads, f32x2 FMA ============
// C_tile = A[M,K] @ B[K,Ntot] (cols cb..cb+127) with epilogue:
//   EPI 0: plain store (QKV; blockIdx.z selects B0/B1/B2, C += z*M*128)
//   EPI 1: C = res + A@B                    (rbf embed)
//   EPI 2: C = silu(A@B + bias)             (FFN up)
//   EPI 3: C = LN(res + A@B [+bias])*g + b  (attn out-proj)
//   EPI 4: EPI3, then gate=tanh(C@Wc+bc); x += gate*(x-px); px=0   (FFN down)
// Each warp (ty) owns rows m0+ty*4 .. +3 across all 128 cols -> row-wise
// LN/gate reductions are full-warp shfl reduces.
template<int EPI>
__global__ void __launch_bounds__(256) gemm128_kernel(
    const float* __restrict__ A, const float* __restrict__ B0,
    const float* __restrict__ B1, const float* __restrict__ B2,
    float* Cb, const float* res, int M, int K, int Ntot,
    const float* __restrict__ bias,
    const float* __restrict__ g, const float* __restrict__ b,
    const float* __restrict__ Wc, const float* __restrict__ bc,
    float* px, float* x)
{
    __shared__ __align__(16) float As2[16 * 34];   // k-major, stride 34 (conflict-free)
    __shared__ __align__(16) float Bs[16][128];
    const float* B = (blockIdx.z == 0) ? B0 : ((blockIdx.z == 1) ? B1 : B2);
    float* C = Cb + (size_t)blockIdx.z * (size_t)M * 128;
    int tid = threadIdx.x;
    int tx = tid & 31, ty = tid >> 5;
    int m0 = blockIdx.y << 5;
    int cb = blockIdx.x << 7;            // column base within Ntot

    ull c2[2][4];
    #pragma unroll
    for (int p = 0; p < 2; p++)
        #pragma unroll
        for (int c = 0; c < 4; c++) c2[p][c] = 0ULL;

    for (int k0 = 0; k0 < K; k0 += 16) {
        if (tid < 128) {
            int m = tid >> 2, k4 = (tid & 3) << 2;
            float4 a4 = *(const float4*)&A[(size_t)(m0 + m) * K + k0 + k4];
            As2[(k4 + 0) * 34 + m] = a4.x;
            As2[(k4 + 1) * 34 + m] = a4.y;
            As2[(k4 + 2) * 34 + m] = a4.z;
            As2[(k4 + 3) * 34 + m] = a4.w;
        }
        #pragma unroll
        for (int u = 0; u < 2; u++) {
            int idx = tid + u * 256;
            int row = idx >> 5, c4 = (idx & 31) << 2;
            *(float4*)&Bs[row][c4] = *(const float4*)&B[(size_t)(k0 + row) * Ntot + cb + c4];
        }
        __syncthreads();
        #pragma unroll
        for (int k = 0; k < 16; k++) {
            float2 a01 = *(const float2*)&As2[k * 34 + ty * 4];
            float2 a23 = *(const float2*)&As2[k * 34 + ty * 4 + 2];
            float4 bv  = *(const float4*)&Bs[k][tx << 2];
            ull A01 = pack2(a01.x, a01.y);
            ull A23 = pack2(a23.x, a23.y);
            ull D0 = dup2(bv.x), D1 = dup2(bv.y), D2 = dup2(bv.z), D3 = dup2(bv.w);
            c2[0][0] = fma2(A01, D0, c2[0][0]);  c2[1][0] = fma2(A23, D0, c2[1][0]);
            c2[0][1] = fma2(A01, D1, c2[0][1]);  c2[1][1] = fma2(A23, D1, c2[1][1]);
            c2[0][2] = fma2(A01, D2, c2[0][2]);  c2[1][2] = fma2(A23, D2, c2[1][2]);
            c2[0][3] = fma2(A01, D3, c2[0][3]);  c2[1][3] = fma2(A23, D3, c2[1][3]);
        }
        __syncthreads();
    }

    // unpack accumulators: val[i][c], rows r = m0 + ty*4 + i, cols cg = cb + tx*4 + c
    float val[4][4];
    #pragma unroll
    for (int p = 0; p < 2; p++)
        #pragma unroll
        for (int c = 0; c < 4; c++) {
            float2 u = unpk(c2[p][c]);
            val[2*p + 0][c] = u.x;
            val[2*p + 1][c] = u.y;
        }
    int cg = cb + (tx << 2);
    int r0 = m0 + ty * 4;

    if (EPI == 0) {
        #pragma unroll
        for (int i = 0; i < 4; i++)
            *(float4*)&C[(size_t)(r0 + i) * Ntot + cg] =
                make_float4(val[i][0], val[i][1], val[i][2], val[i][3]);
        return;
    }
    if (EPI == 1) {
        #pragma unroll
        for (int i = 0; i < 4; i++) {
            float4 rv = *(const float4*)&res[(size_t)(r0 + i) * Ntot + cg];
            *(float4*)&C[(size_t)(r0 + i) * Ntot + cg] =
                make_float4(val[i][0] + rv.x, val[i][1] + rv.y,
                            val[i][2] + rv.z, val[i][3] + rv.w);
        }
        return;
    }
    if (EPI == 2) {
        float4 bv = *(const float4*)&bias[cg];
        #pragma unroll
        for (int i = 0; i < 4; i++) {
            float v0 = val[i][0] + bv.x, v1 = val[i][1] + bv.y;
            float v2 = val[i][2] + bv.z, v3 = val[i][3] + bv.w;
            v0 = v0 / (1.0f + __expf(-v0));
            v1 = v1 / (1.0f + __expf(-v1));
            v2 = v2 / (1.0f + __expf(-v2));
            v3 = v3 / (1.0f + __expf(-v3));
            *(float4*)&C[(size_t)(r0 + i) * Ntot + cg] = make_float4(v0, v1, v2, v3);
        }
        return;
    }

    // EPI 3 / 4: residual (+bias) then row LayerNorm
    float4 bv = make_float4(0.f, 0.f, 0.f, 0.f);
    if (bias) bv = *(const float4*)&bias[cg];
    #pragma unroll
    for (int i = 0; i < 4; i++) {
        float4 rv = *(const float4*)&res[(size_t)(r0 + i) * 128 + cg];
        val[i][0] += rv.x + bv.x;  val[i][1] += rv.y + bv.y;
        val[i][2] += rv.z + bv.z;  val[i][3] += rv.w + bv.w;
    }
    float s[4], sq[4];
    #pragma unroll
    for (int i = 0; i < 4; i++) {
        s[i]  = val[i][0] + val[i][1] + val[i][2] + val[i][3];
        sq[i] = val[i][0]*val[i][0] + val[i][1]*val[i][1]
              + val[i][2]*val[i][2] + val[i][3]*val[i][3];
    }
    #pragma unroll
    for (int o = 16; o > 0; o >>= 1) {
        #pragma unroll
        for (int i = 0; i < 4; i++) {
            s[i]  += __shfl_xor_sync(0xffffffffu, s[i],  o);
            sq[i] += __shfl_xor_sync(0xffffffffu, sq[i], o);
        }
    }
    float4 g4 = *(const float4*)&g[cg];
    float4 b4 = *(const float4*)&b[cg];
    float gd[4];
    float4 wc4 = make_float4(0.f, 0.f, 0.f, 0.f);
    if (EPI == 4) wc4 = *(const float4*)&Wc[cg];
    #pragma unroll
    for (int i = 0; i < 4; i++) {
        float mean = s[i] * (1.0f / 128.0f);
        float var  = fmaxf(sq[i] * (1.0f / 128.0f) - mean * mean, 0.0f);
        float rstd = rsqrtf(var + 1e-5f);
        float h0 = (val[i][0] - mean) * rstd * g4.x + b4.x;
        float h1 = (val[i][1] - mean) * rstd * g4.y + b4.y;
        float h2 = (val[i][2] - mean) * rstd * g4.z + b4.z;
        float h3 = (val[i][3] - mean) * rstd * g4.w + b4.w;
        *(float4*)&C[(size_t)(r0 + i) * 128 + cg] = make_float4(h0, h1, h2, h3);
        if (EPI == 4) gd[i] = h0*wc4.x + h1*wc4.y + h2*wc4.z + h3*wc4.w;
    }
    if (EPI == 4) {
        #pragma unroll
        for (int o = 16; o > 0; o >>= 1)
            #pragma unroll
            for (int i = 0; i < 4; i++)
                gd[i] += __shfl_xor_sync(0xffffffffu, gd[i], o);
        if (tx < 3) {
            float bcv = bc[0];
            #pragma unroll
            for (int i = 0; i < 4; i++) {
                int r = r0 + i;
                float gt = tanhf(gd[i] + bcv);
                float xv = x[r * 3 + tx];
                float pv = px[r * 3 + tx];
                x[r * 3 + tx]  = xv + gt * (xv - pv);
                px[r * 3 + tx] = 0.0f;   // ready for next layer / next replay
            }
        }
    }
}

// ---------------- sparse masked attention: one warp per (query, head) -----------
// Lanes split as (half, d): d = lane&15 is the head-dim, half = lane>>4 splits the
// neighbor list. Streaming softmax; halves merged via shfl at the end.
// In-loop shuffles use per-half masks (halves have different trip counts when n odd).
// INTRA also accumulates px[i] = mean_h sum_j p[h,i,j] * x[j] (atomicAdd, 3 lanes).
template<bool INTRA>
__global__ void __launch_bounds__(256) attn_kernel(
    const float* __restrict__ q, const float* __restrict__ k, const float* __restrict__ v,
    const float* __restrict__ x, float* __restrict__ out, float* __restrict__ px)
{
    int warp = threadIdx.x >> 5, lane = threadIdx.x & 31;
    int i = blockIdx.x * 8 + warp;
    int head = blockIdx.y;
    int off = head * HD_;
    int d = lane & 15, half = lane >> 4;
    unsigned hm = half ? 0xffff0000u : 0x0000ffffu;   // lanes of MY half only

    float qd = q[i * D_ + off + d];
    int n = INTRA ? g_icnt[i] : g_xcnt[i];
    const int* li = (INTRA ? g_ilist : g_xlist) + i * CAP_;

    float m = -1e30f, l = 0.0f, acc = 0.0f, ax = 0.0f;

    for (int t = half; t < n; t += 2) {
        int j = li[t];
        float s = qd * k[j * D_ + off + d];
        s += __shfl_xor_sync(hm, s, 8);
        s += __shfl_xor_sync(hm, s, 4);
        s += __shfl_xor_sync(hm, s, 2);
        s += __shfl_xor_sync(hm, s, 1);
        s *= 0.25f;  // 1/sqrt(16)
        float vd = v[j * D_ + off + d];
        float mn = fmaxf(m, s);
        float cc = __expf(m - mn), p = __expf(s - mn);
        l = l * cc + p;
        acc = acc * cc + p * vd;
        if (INTRA && d < 3) ax = ax * cc + p * x[j * 3 + d];
        m = mn;
    }

    // merge the two halves (all 32 lanes re-converged -> full mask legal)
    float m2 = __shfl_xor_sync(0xffffffffu, m, 16);
    float l2 = __shfl_xor_sync(0xffffffffu, l, 16);
    float a2 = __shfl_xor_sync(0xffffffffu, acc, 16);
    float mn = fmaxf(m, m2);
    float c1 = __expf(m - mn), c2 = __expf(m2 - mn);
    l = l * c1 + l2 * c2;
    acc = acc * c1 + a2 * c2;
    if (INTRA) {
        float x2 = __shfl_xor_sync(0xffffffffu, ax, 16);
        ax = ax * c1 + x2 * c2;
    }
    float inv = 1.0f / l;  // diag always present -> l > 0
    if (half == 0) {
        out[i * D_ + off + d] = acc * inv;
        if (INTRA && d < 3) atomicAdd(&px[i * 3 + d], ax * inv * 0.125f);
    }
}

// ---------------- output: concat(h, x) ----------------
__global__ void out_kernel(const float* __restrict__ h, const float* __restrict__ x,
                           float* __restrict__ out, int out_size)
{
    int i = blockIdx.x * 256 + threadIdx.x;
    if (i >= out_size) return;
    if (i < E_ * D_)               out[i] = h[i];
    else if (i < E_ * D_ + E_ * 3) out[i] = x[i - E_ * D_];
    else                           out[i] = 0.0f;
}

// ---------------- host ----------------
extern "C" void kernel_launch(void* const* d_in, const int* in_sizes, int n_in,
                              void* d_out, int out_size)
{
    const float* edge_features = (const float*)d_in[0];
    const float* edge_coords   = (const float*)d_in[1];
    const int*   edge_index    = (const int*)  d_in[2];
    const float* node_coords   = (const float*)d_in[3];
    const int*   block_ids     = (const int*)  d_in[4];
    const float* Wq_a = (const float*)d_in[5];
    const float* Wk_a = (const float*)d_in[6];
    const float* Wv_a = (const float*)d_in[7];
    const float* Wo_a = (const float*)d_in[8];
    const float* Wq_e = (const float*)d_in[9];
    const float* Wk_e = (const float*)d_in[10];
    const float* Wv_e = (const float*)d_in[11];
    const float* Wo_e = (const float*)d_in[12];
    const float* W1   = (const float*)d_in[13];
    const float* b1   = (const float*)d_in[14];
    const float* W2   = (const float*)d_in[15];
    const float* b2   = (const float*)d_in[16];
    const float* ln1g = (const float*)d_in[17];
    const float* ln1b = (const float*)d_in[18];
    const float* ln2g = (const float*)d_in[19];
    const float* ln2b = (const float*)d_in[20];
    const float* ln3g = (const float*)d_in[21];
    const float* ln3b = (const float*)d_in[22];
    const float* Wrbf = (const float*)d_in[23];
    const float* Wc   = (const float*)d_in[24];
    const float* bc   = (const float*)d_in[25];

    float* buf = nullptr;
    cudaGetSymbolAddress((void**)&buf, g_buf);
    float* h    = buf + OFF_H;
    float* qb   = buf + OFF_Q;     // q,k,v contiguous -> batched GEMM dst
    float* kb   = buf + OFF_K;
    float* vb   = buf + OFF_V;
    float* att  = buf + OFF_ATT;
    float* mid  = buf + OFF_MID;
    float* rbf  = buf + OFF_RBF;
    float* px   = buf + OFF_PX;
    float* xb   = buf + OFF_X;
    int4*  meta = (int4*)(buf + OFF_META);

    dim3 g1(1, E_ / 32, 1);
    dim3 g3(1, E_ / 32, 3);
    dim3 g4(FF_ / 128, E_ / 32, 1);
    dim3 gAttn(E_ / 8, H_);

    prep_kernel<<<(E_ + 127) / 128, 128>>>(edge_index, block_ids, node_coords, meta, rbf, px);
    build_kernel<<<E_, 128>>>(meta);
    copy_kernel<<<(E_ * 3 + 255) / 256, 256>>>(xb, edge_coords, E_ * 3);

    for (int l = 0; l < L_; l++) {
        const int DD = D_ * D_;
        // h = (l==0 ? edge_features : h) + rbf @ Wrbf[l]
        gemm128_kernel<1><<<g1, 256>>>(rbf, Wrbf + l * R_ * D_, nullptr, nullptr,
                                       h, (l == 0) ? edge_features : h,
                                       E_, R_, D_, nullptr, nullptr, nullptr,
                                       nullptr, nullptr, nullptr, nullptr);

        // --- intra attention ---
        gemm128_kernel<0><<<g3, 256>>>(h, Wq_a + l * DD, Wk_a + l * DD, Wv_a + l * DD,
                                       qb, nullptr, E_, D_, D_, nullptr, nullptr, nullptr,
                                       nullptr, nullptr, nullptr, nullptr);
        attn_kernel<true><<<gAttn, 256>>>(qb, kb, vb, xb, att, px);
        gemm128_kernel<3><<<g1, 256>>>(att, Wo_a + l * DD, nullptr, nullptr,
                                       h, h, E_, D_, D_, nullptr,
                                       ln1g + l * D_, ln1b + l * D_,
                                       nullptr, nullptr, nullptr, nullptr);

        // --- inter attention ---
        gemm128_kernel<0><<<g3, 256>>>(h, Wq_e + l * DD, Wk_e + l * DD, Wv_e + l * DD,
                                       qb, nullptr, E_, D_, D_, nullptr, nullptr, nullptr,
                                       nullptr, nullptr, nullptr, nullptr);
        attn_kernel<false><<<gAttn, 256>>>(qb, kb, vb, xb, att, nullptr);
        gemm128_kernel<3><<<g1, 256>>>(att, Wo_e + l * DD, nullptr, nullptr,
                                       h, h, E_, D_, D_, nullptr,
                                       ln2g + l * D_, ln2b + l * D_,
                                       nullptr, nullptr, nullptr, nullptr);

        // --- FFN (down-proj fuses residual+bias+LN+gate+x-update) ---
        gemm128_kernel<2><<<g4, 256>>>(h, W1 + l * D_ * FF_, nullptr, nullptr,
                                       mid, nullptr, E_, D_, FF_, b1 + l * FF_,
                                       nullptr, nullptr, nullptr, nullptr, nullptr, nullptr);
        gemm128_kernel<4><<<g1, 256>>>(mid, W2 + l * FF_ * D_, nullptr, nullptr,
                                       h, h, E_, FF_, D_, b2 + l * D_,
                                       ln3g + l * D_, ln3b + l * D_,
                                       Wc + l * D_, bc + l, px, xb);
    }

    out_kernel<<<(out_size + 255) / 256, 256>>>(h, xb, (float*)d_out, out_size);
}